// round 3
// baseline (speedup 1.0000x reference)
#include <cuda_runtime.h>

#define C_   256
#define H_   50
#define W_   68
#define SCALE 0.0625f
#define TS   76        // smem tile row stride (floats), mult of 4, 76%32=12 for bank spread
#define TS4  19        // in float4
#define MAXROWS 16

__global__ __launch_bounds__(256) void roi_align_kernel(
    const float* __restrict__ feat, const float* __restrict__ rois,
    float* __restrict__ out)
{
    __shared__ float tile[8][MAXROWS * TS];
    __shared__ float sLx[8], sMx[8], sLy[8], sMy[8];
    __shared__ int   sXo[8], sRow0[8], sRow1[8], sRowMul[MAXROWS];
    __shared__ int   sBi, sXb4, sSpanv, sTot;

    const int roi = blockIdx.x;
    const int tid = threadIdx.x;

    if (tid == 0) {
        const float* rp = rois + roi * 5;
        int   bi  = (int)rp[0];
        float x1  = rp[1] * SCALE, y1f = rp[2] * SCALE;
        float x2  = rp[3] * SCALE, y2f = rp[4] * SCALE;
        float rw  = fmaxf(x2 - x1, 0.f), rh = fmaxf(y2f - y1f, 0.f);
        float bw  = rw * (1.f / 7.f),    bh = rh * (1.f / 7.f);
        int x0a[8], y0a[8];
        #pragma unroll
        for (int i = 0; i < 8; i++) {
            float wv = x1 + (float)i * bw;
            int   x0 = min(max((int)floorf(wv), 0), W_ - 2);
            x0a[i] = x0;
            sLx[i] = wv - (float)x0;
            sMx[i] = (wv >= 0.f && wv < (float)W_) ? 1.f : 0.f;
            float hv = y1f + (float)i * bh;
            int   y0 = min(max((int)floorf(hv), 0), H_ - 2);
            y0a[i] = y0;
            sLy[i] = hv - (float)y0;
            sMy[i] = (hv >= 0.f && hv < (float)H_) ? 1.f : 0.f;
        }
        int xlo = x0a[0], xhi = x0a[7] + 1;
        int xb  = xlo & ~3;
        int spanv = ((xhi - xb) >> 2) + 1;          // <=17 float4 per row
        // unique row list (y0 is non-decreasing)
        int n = 0;
        int rowsy[MAXROWS];
        #pragma unroll
        for (int gy = 0; gy < 8; gy++) {
            int a = y0a[gy], bb = a + 1;
            if (n == 0 || rowsy[n - 1] < a) rowsy[n++] = a;
            int ia = (rowsy[n - 1] == a) ? (n - 1) : (n - 2);
            if (rowsy[n - 1] < bb) rowsy[n++] = bb;
            sRow0[gy] = ia * TS;
            sRow1[gy] = (n - 1) * TS;
        }
        for (int r = 0; r < n; r++) sRowMul[r] = rowsy[r] * (W_ / 4);
        #pragma unroll
        for (int i = 0; i < 8; i++) sXo[i] = x0a[i] - xb;
        sBi = bi; sXb4 = xb >> 2; sSpanv = spanv; sTot = n * spanv;
    }
    __syncthreads();

    const int lane = tid & 31, wp = tid >> 5;
    const int gy = lane >> 3, px = lane & 7;

    // per-thread constants, reused across all 32 channels this warp handles
    const float lx  = sLx[px];
    const int   xo  = sXo[px];
    const float lyA = sLy[gy],     mA = sMy[gy]     * sMx[px];
    const float lyB = sLy[gy + 4], mB = sMy[gy + 4] * sMx[px];
    const int   r0A = sRow0[gy],     r1A = sRow1[gy];
    const int   r0B = sRow0[gy + 4], r1B = sRow1[gy + 4];
    const int   tot = sTot, xb4 = sXb4, bi = sBi;
    const unsigned spanv_u = (unsigned)sSpanv;
    const int   spanv = sSpanv;

    const float4* feat4 = (const float4*)feat;
    float*  tl  = tile[wp];
    float4* tl4 = (float4*)tl;
    const unsigned F = 0xffffffffu;

    for (int c = wp; c < C_; c += 8) {
        // ---- stage rows (coalesced float4) ----
        int base4 = (bi * C_ + c) * (H_ * W_ / 4) + xb4;
        for (int t = lane; t < tot; t += 32) {
            unsigned r = (unsigned)t / spanv_u;
            int v = t - (int)r * spanv;
            tl4[r * TS4 + v] = feat4[base4 + sRowMul[r] + v];
        }
        __syncwarp();

        // ---- bilinear grid values: a = grid[gy][px], b = grid[gy+4][px] ----
        float a, b;
        {
            float v00 = tl[r0A + xo], v01 = tl[r0A + xo + 1];
            float v10 = tl[r1A + xo], v11 = tl[r1A + xo + 1];
            float top = v00 + lx * (v01 - v00);
            float bot = v10 + lx * (v11 - v10);
            a = (top + lyA * (bot - top)) * mA;
        }
        {
            float v00 = tl[r0B + xo], v01 = tl[r0B + xo + 1];
            float v10 = tl[r1B + xo], v11 = tl[r1B + xo + 1];
            float top = v00 + lx * (v01 - v00);
            float bot = v10 + lx * (v11 - v10);
            b = (top + lyB * (bot - top)) * mB;
        }

        // ---- 2x2 avg pool via shuffles ----
        float a1 = __shfl_down_sync(F, a, 1);
        float a8 = __shfl_down_sync(F, a, 8);
        float a9 = __shfl_down_sync(F, a, 9);
        float b1 = __shfl_down_sync(F, b, 1);
        float b8 = __shfl_down_sync(F, b, 8);
        float b9 = __shfl_down_sync(F, b, 9);
        float bu0 = __shfl_sync(F, b, (lane + 8) & 31);  // grid[gy+1][px] when gy==3
        float bu1 = __shfl_sync(F, b, (lane + 9) & 31);  // grid[gy+1][px+1] when gy==3
        float da = (gy < 3) ? a8 : bu0;
        float d9 = (gy < 3) ? a9 : bu1;

        int obase = (roi * C_ + c) * 49;
        if (px < 7) {
            out[obase + gy * 7 + px] = (a + a1 + da + d9) * 0.25f;   // oy = 0..3
            if (gy < 3)
                out[obase + 28 + gy * 7 + px] = (b + b1 + b8 + b9) * 0.25f; // oy = 4..6
        }
        __syncwarp();   // tile reuse barrier before next channel
    }
}

extern "C" void kernel_launch(void* const* d_in, const int* in_sizes, int n_in,
                              void* d_out, int out_size) {
    const float* feat = (const float*)d_in[0];
    const float* rois = (const float*)d_in[1];
    float* out = (float*)d_out;
    int R = in_sizes[1] / 5;
    roi_align_kernel<<<R, 256>>>(feat, rois, out);
}

// round 5
// speedup vs baseline: 1.0231x; 1.0231x over previous
#include <cuda_runtime.h>

#define C_   256
#define H_   50
#define W_   68
#define SCALE 0.0625f
#define TS   68        // smem tile row stride (floats); spanv<=17 float4 = 68 floats
#define TS4  17        // in float4
#define MAXROWS 16

__global__ __launch_bounds__(256) void roi_align_kernel(
    const float* __restrict__ feat, const float* __restrict__ rois,
    float* __restrict__ out)
{
    __shared__ float tile[8][MAXROWS * TS];   // 8 * 16 * 68 * 4 = 34816 B
    __shared__ float sLx[8], sMx[8], sLy[8], sMy[8];
    __shared__ int   sXo[8], sRow0[8], sRow1[8], sRowMul[MAXROWS];
    __shared__ int   sBi, sXb4, sSpanv, sTot;

    const int roi = blockIdx.x;
    const int tid = threadIdx.x;

    if (tid == 0) {
        const float* rp = rois + roi * 5;
        int   bi  = (int)rp[0];
        float x1  = rp[1] * SCALE, y1f = rp[2] * SCALE;
        float x2  = rp[3] * SCALE, y2f = rp[4] * SCALE;
        float rw  = fmaxf(x2 - x1, 0.f), rh = fmaxf(y2f - y1f, 0.f);
        float bw  = rw * (1.f / 7.f),    bh = rh * (1.f / 7.f);
        int x0a[8], y0a[8];
        #pragma unroll
        for (int i = 0; i < 8; i++) {
            float wv = x1 + (float)i * bw;
            int   x0 = min(max((int)floorf(wv), 0), W_ - 2);
            x0a[i] = x0;
            sLx[i] = wv - (float)x0;
            sMx[i] = (wv >= 0.f && wv < (float)W_) ? 1.f : 0.f;
            float hv = y1f + (float)i * bh;
            int   y0 = min(max((int)floorf(hv), 0), H_ - 2);
            y0a[i] = y0;
            sLy[i] = hv - (float)y0;
            sMy[i] = (hv >= 0.f && hv < (float)H_) ? 1.f : 0.f;
        }
        int xlo = x0a[0], xhi = x0a[7] + 1;
        int xb  = xlo & ~3;
        int spanv = ((xhi - xb) >> 2) + 1;          // <=17 float4 per row
        // unique row list (y0 is non-decreasing)
        int n = 0;
        int rowsy[MAXROWS];
        #pragma unroll
        for (int gy = 0; gy < 8; gy++) {
            int a = y0a[gy], bb = a + 1;
            if (n == 0 || rowsy[n - 1] < a) rowsy[n++] = a;
            int ia = (rowsy[n - 1] == a) ? (n - 1) : (n - 2);
            if (rowsy[n - 1] < bb) rowsy[n++] = bb;
            sRow0[gy] = ia * TS;
            sRow1[gy] = (n - 1) * TS;
        }
        for (int r = 0; r < n; r++) sRowMul[r] = rowsy[r] * (W_ / 4);
        #pragma unroll
        for (int i = 0; i < 8; i++) sXo[i] = x0a[i] - xb;
        sBi = bi; sXb4 = xb >> 2; sSpanv = spanv; sTot = n * spanv;
    }
    __syncthreads();

    const int lane = tid & 31, wp = tid >> 5;
    const int gy = lane >> 3, px = lane & 7;

    // per-thread constants, reused across all 32 channels this warp handles
    const float lx  = sLx[px];
    const int   xo  = sXo[px];
    const float lyA = sLy[gy],     mA = sMy[gy]     * sMx[px];
    const float lyB = sLy[gy + 4], mB = sMy[gy + 4] * sMx[px];
    const int   r0A = sRow0[gy],     r1A = sRow1[gy];
    const int   r0B = sRow0[gy + 4], r1B = sRow1[gy + 4];
    const int   tot = sTot, xb4 = sXb4, bi = sBi;
    const unsigned spanv_u = (unsigned)sSpanv;
    const int   spanv = sSpanv;

    const float4* feat4 = (const float4*)feat;
    float*  tl  = tile[wp];
    float4* tl4 = (float4*)tl;
    const unsigned F = 0xffffffffu;
    const int srcP = (lane + 1) & 31;   // px+1 within same gy group (px<7 consumers only)
    const int srcV = (lane + 8) & 31;   // next gy group (wraps to b-half row 4 at gy==3)

    for (int c = wp; c < C_; c += 8) {
        // ---- stage rows (coalesced float4) ----
        int base4 = (bi * C_ + c) * (H_ * W_ / 4) + xb4;
        for (int t = lane; t < tot; t += 32) {
            unsigned r = (unsigned)t / spanv_u;
            int v = t - (int)r * spanv;
            tl4[r * TS4 + v] = feat4[base4 + sRowMul[r] + v];
        }
        __syncwarp();

        // ---- bilinear grid values: a = grid[gy][px], b = grid[gy+4][px] ----
        float a, b;
        {
            float v00 = tl[r0A + xo], v01 = tl[r0A + xo + 1];
            float v10 = tl[r1A + xo], v11 = tl[r1A + xo + 1];
            float top = v00 + lx * (v01 - v00);
            float bot = v10 + lx * (v11 - v10);
            a = (top + lyA * (bot - top)) * mA;
        }
        {
            float v00 = tl[r0B + xo], v01 = tl[r0B + xo + 1];
            float v10 = tl[r1B + xo], v11 = tl[r1B + xo + 1];
            float top = v00 + lx * (v01 - v00);
            float bot = v10 + lx * (v11 - v10);
            b = (top + lyB * (bot - top)) * mB;
        }

        // ---- 2x2 avg pool: horizontal pair-sums, then one vertical shuffle ----
        float s_a = a + __shfl_sync(F, a, srcP);   // grid[gy][px] + grid[gy][px+1]
        float s_b = b + __shfl_sync(F, b, srcP);   // grid[gy+4][px] + grid[gy+4][px+1]
        float u_a = __shfl_sync(F, s_a, srcV);     // s_a from gy+1
        float u_b = __shfl_sync(F, s_b, srcV);     // s_b from gy+1 (or row 4 when gy==3)

        int obase = (roi * C_ + c) * 49;
        if (px < 7) {
            float dn = (gy < 3) ? u_a : u_b;       // row gy+1 pair-sum (row 4 at gy==3)
            out[obase + gy * 7 + px] = (s_a + dn) * 0.25f;           // oy = 0..3
            if (gy < 3)
                out[obase + 28 + gy * 7 + px] = (s_b + u_b) * 0.25f; // oy = 4..6
        }
        __syncwarp();   // tile reuse barrier before next channel
    }
}

extern "C" void kernel_launch(void* const* d_in, const int* in_sizes, int n_in,
                              void* d_out, int out_size) {
    const float* feat = (const float*)d_in[0];
    const float* rois = (const float*)d_in[1];
    float* out = (float*)d_out;
    int R = in_sizes[1] / 5;
    roi_align_kernel<<<R, 256>>>(feat, rois, out);
}